// round 2
// baseline (speedup 1.0000x reference)
#include <cuda_runtime.h>

#define B_    16
#define CIN_  512
#define COUT_ 512
#define LAT_  512
#define H_    32
#define W_    32
#define NI_   33      // parity grid extent: i,j in [0,33)

#define CO_BLK 64
#define CCH    16     // ci chunk

// Scratch (device globals: allocation-free rule)
__device__ float g_s[B_ * CIN_];                         // style scale s[b,ci]
__device__ float g_wsq[COUT_ * CIN_];                    // sum_k weight^2
__device__ float g_d[B_ * COUT_];                        // demod factor
__device__ float g_y[(size_t)B_ * COUT_ * 4 * NI_ * NI_];// parity grids [b][co][p][i][j]

// ---------------------------------------------------------------------------
// s[b,ci] = w[b,:] . affine_w[ci,:] + affine_b[ci] + 1
__global__ void k_style(const float* __restrict__ w, const float* __restrict__ aw,
                        const float* __restrict__ ab) {
    int b = blockIdx.x, ci = threadIdx.x;
    const float* wr = w + b * LAT_;
    const float* ar = aw + (size_t)ci * LAT_;
    float acc = 0.f;
#pragma unroll 8
    for (int l = 0; l < LAT_; ++l) acc += wr[l] * ar[l];
    g_s[b * CIN_ + ci] = acc + ab[ci] + 1.0f;
}

// wsq[co,ci] = sum over 3x3 of weight^2
__global__ void k_wsq(const float* __restrict__ weight) {
    int co = blockIdx.x, ci = threadIdx.x;
    const float* p = weight + ((size_t)co * CIN_ + ci) * 9;
    float a = 0.f;
#pragma unroll
    for (int k = 0; k < 9; ++k) a += p[k] * p[k];
    g_wsq[co * CIN_ + ci] = a;
}

// d[b,co] = rsqrt( sum_ci s[b,ci]^2 * wsq[co,ci] + 1e-8 )
__global__ void k_demod() {
    int b = blockIdx.x, co = threadIdx.x;
    __shared__ float s2[CIN_];
    for (int i = threadIdx.x; i < CIN_; i += blockDim.x) {
        float v = g_s[b * CIN_ + i];
        s2[i] = v * v;
    }
    __syncthreads();
    const float* wq = g_wsq + (size_t)co * CIN_;
    float a = 0.f;
#pragma unroll 8
    for (int ci = 0; ci < CIN_; ++ci) a += s2[ci] * wq[ci];
    g_d[b * COUT_ + co] = rsqrtf(a + 1e-8f);
}

// ---------------------------------------------------------------------------
// ConvTranspose (stride 2, 3x3) as 4 parity grids over (i,j) in [0,33)^2:
//  y[2i+a, 2j+c] = sum_ci sum_{kh%2==a, kw%2==c} W[co,ci,kh,kw] * xs[ci, i-(kh>>1), j-(kw>>1)]
// xs = s*x, zero-padded (x[-1]=x[32]=0).
__global__ __launch_bounds__(256, 2) void k_conv(const float* __restrict__ x,
                                                 const float* __restrict__ weight) {
    __shared__ float xs[CCH][9][12];        // rows i0-1..i0+7, cols j0-1..j0+7
    __shared__ float ws[CCH][9][CO_BLK];    // [ci][k][co]

    const int tid   = threadIdx.x;
    const int co_t  = tid & 15;             // 16 co-groups of 4
    const int pos_t = tid >> 4;             // 16 position threads
    const int it    = pos_t >> 1;           // 0..7 (one i-row per thread)
    const int jt    = pos_t & 1;            // 0..1 (4 j each)
    const int ti = blockIdx.x / 5, tj = blockIdx.x % 5;
    const int i0 = ti * 8, j0 = tj * 8;
    const int co_base = blockIdx.y * CO_BLK;
    const int b = blockIdx.z;

    float acc[4][4][4];                     // [parity][cc][jj]
#pragma unroll
    for (int p = 0; p < 4; ++p)
#pragma unroll
        for (int c = 0; c < 4; ++c)
#pragma unroll
            for (int j = 0; j < 4; ++j) acc[p][c][j] = 0.f;

    const int  i       = i0 + it;
    const bool compute = (i < NI_);         // warp-uniform (it uniform per warp)
    const float* sb = g_s + b * CIN_;

    for (int c0 = 0; c0 < CIN_; c0 += CCH) {
        __syncthreads();
        // x tile (with zero padding + s scale)
        for (int idx = tid; idx < CCH * 81; idx += 256) {
            int ci = idx / 81, rem = idx - ci * 81;
            int r = rem / 9, c = rem - r * 9;
            int gi = i0 - 1 + r, gj = j0 - 1 + c;
            float v = 0.f;
            if ((unsigned)gi < H_ && (unsigned)gj < W_)
                v = x[(((size_t)b * CIN_ + c0 + ci) * H_ + gi) * W_ + gj] * sb[c0 + ci];
            xs[ci][r][c] = v;
        }
        // weight tile -> [ci][k][co]
        for (int idx = tid; idx < CCH * 9 * CO_BLK; idx += 256) {
            int co = idx / (CCH * 9), rem = idx - co * (CCH * 9);
            int ci = rem / 9, k = rem - ci * 9;
            ws[ci][k][co] = weight[(((size_t)(co_base + co)) * CIN_ + c0 + ci) * 9 + k];
        }
        __syncthreads();
        if (!compute) continue;

#pragma unroll 4
        for (int ci = 0; ci < CCH; ++ci) {
            float x0[5], x1[5];
            const int cb = jt * 4;
#pragma unroll
            for (int m = 0; m < 5; ++m) {
                x0[m] = xs[ci][it][cb + m];      // row i-1
                x1[m] = xs[ci][it + 1][cb + m];  // row i
            }
#pragma unroll
            for (int k = 0; k < 9; ++k) {
                const float4 w4 = *(const float4*)&ws[ci][k][co_t * 4];
                const int kh = k / 3, kw = k % 3;
                const int p  = (kh & 1) * 2 + (kw & 1);
                const int dy = kh >> 1, dx = kw >> 1;
                const float wv[4] = {w4.x, w4.y, w4.z, w4.w};
#pragma unroll
                for (int cc = 0; cc < 4; ++cc) {
#pragma unroll
                    for (int jj = 0; jj < 4; ++jj) {
                        const float xv = (dy ? x0 : x1)[jj + 1 - dx];
                        acc[p][cc][jj] += wv[cc] * xv;
                    }
                }
            }
        }
    }

    if (compute) {
        const size_t cobase = (size_t)b * COUT_ + co_base + co_t * 4;
#pragma unroll
        for (int cc = 0; cc < 4; ++cc) {
#pragma unroll
            for (int p = 0; p < 4; ++p) {
                float* yp = g_y + (((cobase + cc) * 4 + p) * NI_ + i) * NI_;
#pragma unroll
                for (int jj = 0; jj < 4; ++jj) {
                    int j = j0 + jt * 4 + jj;
                    if (j < NI_) yp[j] = acc[p][cc][jj];
                }
            }
        }
    }
}

// ---------------------------------------------------------------------------
// Blur 4x4 ([1,3,3,1] outer /16) over the de-interleaved 65x65 y, pad 1,
// scaled by d[b,co], plus bias. Output z[b,co,64,64].
__global__ __launch_bounds__(256) void k_blur(float* __restrict__ z,
                                              const float* __restrict__ bias) {
    __shared__ float ys[67][68];   // ys[r+1][s+1] = y[r][s], zero borders
    const int co = blockIdx.x, b = blockIdx.y;
    const int tid = threadIdx.x;

    for (int idx = tid; idx < 67 * 68; idx += 256) ((float*)ys)[idx] = 0.f;
    __syncthreads();

    const float* yp = g_y + ((size_t)(b * COUT_ + co)) * 4 * NI_ * NI_;
    for (int idx = tid; idx < 4 * NI_ * NI_; idx += 256) {
        int p = idx / (NI_ * NI_), rem = idx - p * (NI_ * NI_);
        int i = rem / NI_, j = rem - i * NI_;
        int a = p >> 1, c = p & 1;
        ys[2 * i + a + 1][2 * j + c + 1] = yp[idx];
    }
    __syncthreads();

    const float dd = g_d[b * COUT_ + co];
    const float bv = bias[co];
    const int u  = tid >> 2;          // 0..63
    const int v0 = (tid & 3) * 16;    // 16 outputs per thread

    float col[19];
#pragma unroll
    for (int m = 0; m < 19; ++m) {
        // vertical taps y[u-1..u+2] -> ys[u..u+3]
        col[m] = ys[u][v0 + m] + 3.f * ys[u + 1][v0 + m]
               + 3.f * ys[u + 2][v0 + m] + ys[u + 3][v0 + m];
    }
    float* zp = z + (((size_t)b * COUT_ + co) * 64 + u) * 64 + v0;
#pragma unroll
    for (int m = 0; m < 16; ++m) {
        float h = col[m] + 3.f * col[m + 1] + 3.f * col[m + 2] + col[m + 3];
        zp[m] = dd * (h * (1.f / 16.f)) + bv;
    }
}

// ---------------------------------------------------------------------------
extern "C" void kernel_launch(void* const* d_in, const int* in_sizes, int n_in,
                              void* d_out, int out_size) {
    const float* x    = (const float*)d_in[0];
    const float* w    = (const float*)d_in[1];
    const float* wt   = (const float*)d_in[2];
    const float* bias = (const float*)d_in[3];
    const float* aw   = (const float*)d_in[4];
    const float* ab   = (const float*)d_in[5];
    float* z = (float*)d_out;

    k_style<<<B_, CIN_>>>(w, aw, ab);
    k_wsq<<<COUT_, CIN_>>>(wt);
    k_demod<<<B_, COUT_>>>();
    k_conv<<<dim3(25, COUT_ / CO_BLK, B_), 256>>>(x, wt);
    k_blur<<<dim3(COUT_, B_), 256>>>(z, bias);
}

// round 5
// speedup vs baseline: 4.7936x; 4.7936x over previous
#include <cuda_runtime.h>
#include <cuda_bf16.h>
#include <cstdint>

#define B_    16
#define CIN_  512
#define COUT_ 512
#define LAT_  512

#define XROWS  18496            // 16 * 34 * 34
#define XGUARD 64
#define NTILES 145              // ceil(18496/128)

// ---------------- device globals (allocation-free scratch) ------------------
__device__ float g_s[B_ * CIN_];
__device__ float g_wsq[COUT_ * CIN_];
__device__ float g_d[B_ * COUT_];
__device__ float g_y[(size_t)B_ * COUT_ * 4 * 1156];     // [b][co][p][34][34]

__device__ __align__(256) __nv_bfloat16 g_Ah[9ull * 512 * 512];   // [tap][co][ci]
__device__ __align__(256) __nv_bfloat16 g_Al[9ull * 512 * 512];
__device__ __align__(256) __nv_bfloat16 g_Xh[(size_t)(XROWS + 2 * XGUARD) * 512];
__device__ __align__(256) __nv_bfloat16 g_Xl[(size_t)(XROWS + 2 * XGUARD) * 512];

// tap order grouped by parity: p0={0,2,6,8} p1={1,7} p2={3,5} p3={4}
__constant__ int c_tap[9]   = {0, 2, 6, 8, 1, 7, 3, 5, 4};
// shift[t] = (kh>>1)*34 + (kw>>1), indexed by tap id
__constant__ int c_shift[9] = {0, 0, 1, 0, 0, 1, 34, 34, 35};

// ---------------- helpers ---------------------------------------------------
__device__ __forceinline__ uint32_t smem_to_u32(const void* p) {
    uint32_t a;
    asm("{ .reg .u64 t; cvta.to.shared.u64 t, %1; cvt.u32.u64 %0, t; }"
        : "=r"(a) : "l"(p));
    return a;
}
__device__ __forceinline__ void cp16(uint32_t dst, const void* src) {
    asm volatile("cp.async.cg.shared.global [%0], [%1], 16;\n"
                 :: "r"(dst), "l"(src));
}
__device__ __forceinline__ void cp_commit() {
    asm volatile("cp.async.commit_group;\n" ::: "memory");
}
__device__ __forceinline__ void cp_wait2() {
    asm volatile("cp.async.wait_group 2;\n" ::: "memory");
}
__device__ __forceinline__ void ldsm_x4(uint32_t* r, uint32_t addr) {
    asm volatile("ldmatrix.sync.aligned.m8n8.x4.shared.b16 {%0,%1,%2,%3}, [%4];"
                 : "=r"(r[0]), "=r"(r[1]), "=r"(r[2]), "=r"(r[3]) : "r"(addr));
}
__device__ __forceinline__ void mma_bf16(float* d, const uint32_t* a,
                                         const uint32_t* b) {
    asm volatile(
        "mma.sync.aligned.m16n8k16.row.col.f32.bf16.bf16.f32 "
        "{%0,%1,%2,%3}, {%4,%5,%6,%7}, {%8,%9}, {%0,%1,%2,%3};"
        : "+f"(d[0]), "+f"(d[1]), "+f"(d[2]), "+f"(d[3])
        : "r"(a[0]), "r"(a[1]), "r"(a[2]), "r"(a[3]), "r"(b[0]), "r"(b[1]));
}
// smem tile: 128 rows x 32 bf16 (64B rows), xor-swizzled 16B chunks
__device__ __forceinline__ int swz(int row, int c8) {
    return row * 64 + ((c8 ^ ((row >> 1) & 3)) << 4);
}

// ---------------------------------------------------------------------------
__global__ void k_style(const float* __restrict__ w, const float* __restrict__ aw,
                        const float* __restrict__ ab) {
    int b = blockIdx.x, ci = threadIdx.x;
    const float* wr = w + b * LAT_;
    const float* ar = aw + (size_t)ci * LAT_;
    float acc = 0.f;
#pragma unroll 8
    for (int l = 0; l < LAT_; ++l) acc += wr[l] * ar[l];
    g_s[b * CIN_ + ci] = acc + ab[ci] + 1.0f;
}

__global__ void k_wsq(const float* __restrict__ weight) {
    int co = blockIdx.x, ci = threadIdx.x;
    const float* p = weight + ((size_t)co * CIN_ + ci) * 9;
    float a = 0.f;
#pragma unroll
    for (int k = 0; k < 9; ++k) a += p[k] * p[k];
    g_wsq[co * CIN_ + ci] = a;
}

__global__ void k_demod() {
    int b = blockIdx.x, co = threadIdx.x;
    __shared__ float s2[CIN_];
    for (int i = threadIdx.x; i < CIN_; i += blockDim.x) {
        float v = g_s[b * CIN_ + i];
        s2[i] = v * v;
    }
    __syncthreads();
    const float* wq = g_wsq + (size_t)co * CIN_;
    float a = 0.f;
#pragma unroll 8
    for (int ci = 0; ci < CIN_; ++ci) a += s2[ci] * wq[ci];
    g_d[b * COUT_ + co] = rsqrtf(a + 1e-8f);
}

// A prep: g_A[tap][co][ci] = weight[co][ci][tap], hi/lo bf16
__global__ __launch_bounds__(256) void k_prepw(const float* __restrict__ weight) {
    int co = blockIdx.x;
    for (int idx = threadIdx.x; idx < 9 * 512; idx += 256) {
        int t = idx / 512, ci = idx & 511;
        float v = weight[((size_t)co * 512 + ci) * 9 + t];
        __nv_bfloat16 h = __float2bfloat16(v);
        __nv_bfloat16 l = __float2bfloat16(v - __bfloat162float(h));
        size_t o = ((size_t)t * 512 + co) * 512 + ci;
        g_Ah[o] = h;
        g_Al[o] = l;
    }
}

// Xp prep: row n'' = b*1156 + r*34 + c ; Xp = x*s interior, 0 on r,c in {0,33}
__global__ __launch_bounds__(256) void k_prepx(const float* __restrict__ x) {
    __shared__ float xt[256][33];
    const int r = blockIdx.x;          // 0..33
    const int b = blockIdx.y;
    const int tid = threadIdx.x;
    const bool irow = (r >= 1 && r <= 32);
    for (int half = 0; half < 2; ++half) {
        const int cb = half * 256;
        __syncthreads();
        if (irow) {
            for (int idx = tid; idx < 256 * 32; idx += 256) {
                int ci = idx >> 5, cc = idx & 31;
                xt[ci][cc] = x[((size_t)(b * 512 + cb + ci) * 32 + (r - 1)) * 32 + cc]
                             * g_s[b * 512 + cb + ci];
            }
        }
        __syncthreads();
        for (int idx = tid; idx < 34 * 256; idx += 256) {
            int c = idx >> 8, ci = idx & 255;
            float v = (irow && c >= 1 && c <= 32) ? xt[ci][c - 1] : 0.f;
            __nv_bfloat16 h = __float2bfloat16(v);
            __nv_bfloat16 l = __float2bfloat16(v - __bfloat162float(h));
            size_t o = ((size_t)(b * 1156 + r * 34 + c) + XGUARD) * 512 + cb + ci;
            g_Xh[o] = h;
            g_Xl[o] = l;
        }
    }
}

__global__ void k_guard() {
    int idx = blockIdx.x * 256 + threadIdx.x;       // 65536 total
    __nv_bfloat16 z = __float2bfloat16(0.f);
    if (idx < XGUARD * 512) {
        g_Xh[idx] = z;
        g_Xl[idx] = z;
    } else {
        size_t o = (size_t)(XGUARD + XROWS) * 512 + (idx - XGUARD * 512);
        g_Xh[o] = z;
        g_Xl[o] = z;
    }
}

// ---------------------------------------------------------------------------
#define STAGES      3
#define TILE_AH     0
#define TILE_AL     8192
#define TILE_BH     16384
#define TILE_BL     24576
#define STAGE_BYTES 32768

__device__ __forceinline__ void load_chunk(uint32_t su, int stage, int g,
                                           int co0, int n0, int tid) {
    const int tap = c_tap[g >> 4];
    const int kc  = (g & 15) << 5;
    const int row = tid >> 1;
    const int cp  = tid & 1;
    const uint32_t sb = su + stage * STAGE_BYTES;
    const int s0 = swz(row, 2 * cp);
    const int s1 = swz(row, 2 * cp + 1);

    size_t aoff = ((size_t)(tap * 512 + co0 + row)) * 512 + kc + cp * 16;
    cp16(sb + TILE_AH + s0, g_Ah + aoff);
    cp16(sb + TILE_AH + s1, g_Ah + aoff + 8);
    cp16(sb + TILE_AL + s0, g_Al + aoff);
    cp16(sb + TILE_AL + s1, g_Al + aoff + 8);

    long brow = (long)n0 - c_shift[tap] + row + XGUARD;
    size_t boff = (size_t)brow * 512 + kc + cp * 16;
    cp16(sb + TILE_BH + s0, g_Xh + boff);
    cp16(sb + TILE_BH + s1, g_Xh + boff + 8);
    cp16(sb + TILE_BL + s0, g_Xl + boff);
    cp16(sb + TILE_BL + s1, g_Xl + boff + 8);
}

__device__ __forceinline__ void do_compute(uint32_t sb, float acc[4][4][4],
                                           int lane, int warp_m, int warp_n) {
#pragma unroll
    for (int ks = 0; ks < 2; ++ks) {
        uint32_t bh[8], bl[8];
#pragma unroll
        for (int pr = 0; pr < 2; ++pr) {
            int brow = warp_n + pr * 16 + (lane & 7) + ((lane >> 4) & 1) * 8;
            int bc8  = ks * 2 + ((lane >> 3) & 1);
            uint32_t ad = sb + TILE_BH + swz(brow, bc8);
            ldsm_x4(&bh[pr * 4], ad);
            ldsm_x4(&bl[pr * 4], ad + (TILE_BL - TILE_BH));
        }
#pragma unroll
        for (int mt = 0; mt < 4; ++mt) {
            int arow = warp_m + mt * 16 + (lane & 15);
            int ac8  = ks * 2 + ((lane >> 4) & 1);
            uint32_t ad = sb + TILE_AH + swz(arow, ac8);
            uint32_t ah[4], al[4];
            ldsm_x4(ah, ad);
            ldsm_x4(al, ad + (TILE_AL - TILE_AH));
#pragma unroll
            for (int nt = 0; nt < 4; ++nt) {
                const uint32_t* fh = &bh[(nt >> 1) * 4 + (nt & 1) * 2];
                const uint32_t* fl = &bl[(nt >> 1) * 4 + (nt & 1) * 2];
                mma_bf16(acc[mt][nt], ah, fh);
                mma_bf16(acc[mt][nt], ah, fl);
                mma_bf16(acc[mt][nt], al, fh);
            }
        }
    }
}

__device__ __forceinline__ void epilogue(float acc[4][4][4], int p, int co0,
                                         int n0, int lane, int warp_m, int warp_n) {
    const int rr = lane >> 2, q = lane & 3;
#pragma unroll
    for (int mt = 0; mt < 4; ++mt) {
        const int co = co0 + warp_m + mt * 16 + rr;
#pragma unroll
        for (int nt = 0; nt < 4; ++nt) {
            int n = n0 + warp_n + nt * 8 + q * 2;
            if (n < XROWS) {
                int b = n / 1156;
                int rem = n - b * 1156;
                float2 v0 = make_float2(acc[mt][nt][0], acc[mt][nt][1]);
                float2 v1 = make_float2(acc[mt][nt][2], acc[mt][nt][3]);
                *(float2*)(g_y + (((size_t)(b * 512 + co) * 4 + p) * 1156 + rem)) = v0;
                *(float2*)(g_y + (((size_t)(b * 512 + co + 8) * 4 + p) * 1156 + rem)) = v1;
            }
        }
    }
}

__global__ __launch_bounds__(256, 2) void k_gemm() {
    extern __shared__ char smem[];
    const uint32_t su = smem_to_u32(smem);
    const int tid = threadIdx.x;
    const int lane = tid & 31, wid = tid >> 5;
    const int warp_m = (wid >> 2) * 64;
    const int warp_n = (wid & 3) * 32;
    const int n0  = blockIdx.x * 128;
    const int co0 = blockIdx.y * 128;

    float acc[4][4][4];
#pragma unroll
    for (int a = 0; a < 4; ++a)
#pragma unroll
        for (int b = 0; b < 4; ++b)
#pragma unroll
            for (int c = 0; c < 4; ++c) acc[a][b][c] = 0.f;

#pragma unroll
    for (int s = 0; s < STAGES; ++s) {
        load_chunk(su, s, s, co0, n0, tid);
        cp_commit();
    }

    for (int g = 0; g < 144; ++g) {
        cp_wait2();
        __syncthreads();
        do_compute(su + (g % STAGES) * STAGE_BYTES, acc, lane, warp_m, warp_n);
        if (g == 63 || g == 95 || g == 127 || g == 143) {
            const int p = (g == 63) ? 0 : (g == 95) ? 1 : (g == 127) ? 2 : 3;
            epilogue(acc, p, co0, n0, lane, warp_m, warp_n);
#pragma unroll
            for (int a = 0; a < 4; ++a)
#pragma unroll
                for (int b = 0; b < 4; ++b)
#pragma unroll
                    for (int c = 0; c < 4; ++c) acc[a][b][c] = 0.f;
        }
        __syncthreads();
        if (g + STAGES < 144)
            load_chunk(su, (g + STAGES) % STAGES, g + STAGES, co0, n0, tid);
        cp_commit();
    }
}

// ---------------------------------------------------------------------------
__global__ __launch_bounds__(256) void k_blur(float* __restrict__ z,
                                              const float* __restrict__ bias) {
    __shared__ float ys[67][68];
    const int co = blockIdx.x, b = blockIdx.y;
    const int tid = threadIdx.x;

    for (int idx = tid; idx < 67 * 68; idx += 256) ((float*)ys)[idx] = 0.f;
    __syncthreads();

    const float* yb = g_y + ((size_t)(b * 512 + co)) * 4 * 1156;
    for (int idx = tid; idx < 4 * 33 * 33; idx += 256) {
        int p = idx / 1089, rem = idx - p * 1089;
        int i = rem / 33, j = rem - i * 33;
        float v = yb[(size_t)p * 1156 + (i + 1) * 34 + (j + 1)];
        ys[2 * i + (p >> 1) + 1][2 * j + (p & 1) + 1] = v;
    }
    __syncthreads();

    const float dd = g_d[b * COUT_ + co];
    const float bv = bias[co];
    const int u = tid >> 2;
    const int v0 = (tid & 3) * 16;

    float col[19];
#pragma unroll
    for (int m = 0; m < 19; ++m) {
        col[m] = ys[u][v0 + m] + 3.f * ys[u + 1][v0 + m]
               + 3.f * ys[u + 2][v0 + m] + ys[u + 3][v0 + m];
    }
    float* zp = z + (((size_t)b * COUT_ + co) * 64 + u) * 64 + v0;
#pragma unroll
    for (int m = 0; m < 16; ++m) {
        float h = col[m] + 3.f * col[m + 1] + 3.f * col[m + 2] + col[m + 3];
        zp[m] = dd * (h * (1.f / 16.f)) + bv;
    }
}

// ---------------------------------------------------------------------------
extern "C" void kernel_launch(void* const* d_in, const int* in_sizes, int n_in,
                              void* d_out, int out_size) {
    const float* x    = (const float*)d_in[0];
    const float* w    = (const float*)d_in[1];
    const float* wt   = (const float*)d_in[2];
    const float* bias = (const float*)d_in[3];
    const float* aw   = (const float*)d_in[4];
    const float* ab   = (const float*)d_in[5];
    float* z = (float*)d_out;

    cudaFuncSetAttribute(k_gemm, cudaFuncAttributeMaxDynamicSharedMemorySize,
                         STAGES * STAGE_BYTES);

    k_style<<<B_, CIN_>>>(w, aw, ab);
    k_prepx<<<dim3(34, B_), 256>>>(x);
    k_guard<<<256, 256>>>();
    k_prepw<<<COUT_, 256>>>(wt);
    k_wsq<<<COUT_, CIN_>>>(wt);
    k_demod<<<B_, COUT_>>>();
    k_gemm<<<dim3(NTILES, 4), 256, STAGES * STAGE_BYTES>>>();
    k_blur<<<dim3(COUT_, B_), 256>>>(z, bias);
}

// round 6
// speedup vs baseline: 6.0526x; 1.2626x over previous
#include <cuda_runtime.h>
#include <cuda_fp16.h>
#include <cstdint>

#define B_    16
#define CIN_  512
#define COUT_ 512
#define LAT_  512

#define XROWS  18496            // 16 * 34 * 34
#define XGUARD 64
#define NTILES 145              // ceil(18496/128)

// ---------------- device globals (allocation-free scratch) ------------------
__device__ float g_s[B_ * CIN_];
__device__ float g_wsq[COUT_ * CIN_];
__device__ float g_d[B_ * COUT_];
__device__ float g_y[(size_t)B_ * COUT_ * 4 * 1156];     // [b][co][p][34][34]

__device__ __align__(256) __half g_Ah[9ull * 512 * 512];   // [tap][co][ci]
__device__ __align__(256) __half g_Al[9ull * 512 * 512];
__device__ __align__(256) __half g_Xh[(size_t)(XROWS + 2 * XGUARD) * 512];

// tap order grouped by parity: p0={0,2,6,8} p1={1,7} p2={3,5} p3={4}
__constant__ int c_tap[9]   = {0, 2, 6, 8, 1, 7, 3, 5, 4};
// shift[t] = (kh>>1)*34 + (kw>>1), indexed by tap id
__constant__ int c_shift[9] = {0, 0, 1, 0, 0, 1, 34, 34, 35};

// ---------------- helpers ---------------------------------------------------
__device__ __forceinline__ uint32_t smem_to_u32(const void* p) {
    uint32_t a;
    asm("{ .reg .u64 t; cvta.to.shared.u64 t, %1; cvt.u32.u64 %0, t; }"
        : "=r"(a) : "l"(p));
    return a;
}
__device__ __forceinline__ void cp16(uint32_t dst, const void* src) {
    asm volatile("cp.async.cg.shared.global [%0], [%1], 16;\n"
                 :: "r"(dst), "l"(src));
}
__device__ __forceinline__ void cp_commit() {
    asm volatile("cp.async.commit_group;\n" ::: "memory");
}
__device__ __forceinline__ void cp_wait2() {
    asm volatile("cp.async.wait_group 2;\n" ::: "memory");
}
__device__ __forceinline__ void ldsm_x4(uint32_t* r, uint32_t addr) {
    asm volatile("ldmatrix.sync.aligned.m8n8.x4.shared.b16 {%0,%1,%2,%3}, [%4];"
                 : "=r"(r[0]), "=r"(r[1]), "=r"(r[2]), "=r"(r[3]) : "r"(addr));
}
__device__ __forceinline__ void mma_fp16(float* d, const uint32_t* a,
                                         const uint32_t* b) {
    asm volatile(
        "mma.sync.aligned.m16n8k16.row.col.f32.f16.f16.f32 "
        "{%0,%1,%2,%3}, {%4,%5,%6,%7}, {%8,%9}, {%0,%1,%2,%3};"
        : "+f"(d[0]), "+f"(d[1]), "+f"(d[2]), "+f"(d[3])
        : "r"(a[0]), "r"(a[1]), "r"(a[2]), "r"(a[3]), "r"(b[0]), "r"(b[1]));
}
// smem tile: 128 rows x 32 fp16 (64B rows), xor-swizzled 16B chunks
__device__ __forceinline__ int swz(int row, int c8) {
    return row * 64 + ((c8 ^ ((row >> 1) & 3)) << 4);
}

// ---------------------------------------------------------------------------
__global__ void k_style(const float* __restrict__ w, const float* __restrict__ aw,
                        const float* __restrict__ ab) {
    int b = blockIdx.x, ci = threadIdx.x;
    const float* wr = w + b * LAT_;
    const float* ar = aw + (size_t)ci * LAT_;
    float acc = 0.f;
#pragma unroll 8
    for (int l = 0; l < LAT_; ++l) acc += wr[l] * ar[l];
    g_s[b * CIN_ + ci] = acc + ab[ci] + 1.0f;
}

__global__ void k_wsq(const float* __restrict__ weight) {
    int co = blockIdx.x, ci = threadIdx.x;
    const float* p = weight + ((size_t)co * CIN_ + ci) * 9;
    float a = 0.f;
#pragma unroll
    for (int k = 0; k < 9; ++k) a += p[k] * p[k];
    g_wsq[co * CIN_ + ci] = a;
}

__global__ void k_demod() {
    int b = blockIdx.x, co = threadIdx.x;
    __shared__ float s2[CIN_];
    for (int i = threadIdx.x; i < CIN_; i += blockDim.x) {
        float v = g_s[b * CIN_ + i];
        s2[i] = v * v;
    }
    __syncthreads();
    const float* wq = g_wsq + (size_t)co * CIN_;
    float a = 0.f;
#pragma unroll 8
    for (int ci = 0; ci < CIN_; ++ci) a += s2[ci] * wq[ci];
    g_d[b * COUT_ + co] = rsqrtf(a + 1e-8f);
}

// A prep: g_A[tap][co][ci] = weight[co][ci][tap], hi/lo fp16
__global__ __launch_bounds__(256) void k_prepw(const float* __restrict__ weight) {
    int co = blockIdx.x;
    for (int idx = threadIdx.x; idx < 9 * 512; idx += 256) {
        int t = idx / 512, ci = idx & 511;
        float v = weight[((size_t)co * 512 + ci) * 9 + t];
        __half h = __float2half_rn(v);
        __half l = __float2half_rn(v - __half2float(h));
        size_t o = ((size_t)t * 512 + co) * 512 + ci;
        g_Ah[o] = h;
        g_Al[o] = l;
    }
}

// Xp prep: row n = b*1156 + r*34 + c ; Xp = x*s interior, 0 on r,c in {0,33}
__global__ __launch_bounds__(256) void k_prepx(const float* __restrict__ x) {
    __shared__ float xt[256][33];
    const int r = blockIdx.x;          // 0..33
    const int b = blockIdx.y;
    const int tid = threadIdx.x;
    const bool irow = (r >= 1 && r <= 32);
    for (int half = 0; half < 2; ++half) {
        const int cb = half * 256;
        __syncthreads();
        if (irow) {
            for (int idx = tid; idx < 256 * 32; idx += 256) {
                int ci = idx >> 5, cc = idx & 31;
                xt[ci][cc] = x[((size_t)(b * 512 + cb + ci) * 32 + (r - 1)) * 32 + cc]
                             * g_s[b * 512 + cb + ci];
            }
        }
        __syncthreads();
        for (int idx = tid; idx < 34 * 256; idx += 256) {
            int c = idx >> 8, ci = idx & 255;
            float v = (irow && c >= 1 && c <= 32) ? xt[ci][c - 1] : 0.f;
            size_t o = ((size_t)(b * 1156 + r * 34 + c) + XGUARD) * 512 + cb + ci;
            g_Xh[o] = __float2half_rn(v);
        }
    }
}

__global__ void k_guard() {
    int idx = blockIdx.x * 256 + threadIdx.x;       // 65536 total
    __half z = __float2half_rn(0.f);
    if (idx < XGUARD * 512) {
        g_Xh[idx] = z;
    } else {
        g_Xh[(size_t)(XGUARD + XROWS) * 512 + (idx - XGUARD * 512)] = z;
    }
}

// ---------------------------------------------------------------------------
#define STAGES      4
#define TILE_AH     0
#define TILE_AL     8192
#define TILE_BH     16384
#define STAGE_BYTES 24576

__device__ __forceinline__ void load_chunk(uint32_t su, int stage, int g,
                                           int co0, int n0, int tid) {
    const int tap = c_tap[g >> 4];
    const int kc  = (g & 15) << 5;
    const int row = tid >> 1;
    const int cp  = tid & 1;
    const uint32_t sb = su + stage * STAGE_BYTES;
    const int s0 = swz(row, 2 * cp);
    const int s1 = swz(row, 2 * cp + 1);

    size_t aoff = ((size_t)(tap * 512 + co0 + row)) * 512 + kc + cp * 16;
    cp16(sb + TILE_AH + s0, g_Ah + aoff);
    cp16(sb + TILE_AH + s1, g_Ah + aoff + 8);
    cp16(sb + TILE_AL + s0, g_Al + aoff);
    cp16(sb + TILE_AL + s1, g_Al + aoff + 8);

    long brow = (long)n0 - c_shift[tap] + row + XGUARD;
    size_t boff = (size_t)brow * 512 + kc + cp * 16;
    cp16(sb + TILE_BH + s0, g_Xh + boff);
    cp16(sb + TILE_BH + s1, g_Xh + boff + 8);
}

__device__ __forceinline__ void do_compute(uint32_t sb, float acc[4][4][4],
                                           int lane, int warp_m, int warp_n) {
#pragma unroll
    for (int ks = 0; ks < 2; ++ks) {
        uint32_t bh[8];
#pragma unroll
        for (int pr = 0; pr < 2; ++pr) {
            int brow = warp_n + pr * 16 + (lane & 7) + ((lane >> 4) & 1) * 8;
            int bc8  = ks * 2 + ((lane >> 3) & 1);
            ldsm_x4(&bh[pr * 4], sb + TILE_BH + swz(brow, bc8));
        }
#pragma unroll
        for (int mt = 0; mt < 4; ++mt) {
            int arow = warp_m + mt * 16 + (lane & 15);
            int ac8  = ks * 2 + ((lane >> 4) & 1);
            uint32_t ad = sb + TILE_AH + swz(arow, ac8);
            uint32_t ah[4], al[4];
            ldsm_x4(ah, ad);
            ldsm_x4(al, ad + (TILE_AL - TILE_AH));
#pragma unroll
            for (int nt = 0; nt < 4; ++nt) {
                const uint32_t* fh = &bh[(nt >> 1) * 4 + (nt & 1) * 2];
                mma_fp16(acc[mt][nt], ah, fh);
                mma_fp16(acc[mt][nt], al, fh);
            }
        }
    }
}

__device__ __forceinline__ void epilogue(float acc[4][4][4], int p, int co0,
                                         int n0, int lane, int warp_m, int warp_n) {
    const int rr = lane >> 2, q = lane & 3;
#pragma unroll
    for (int mt = 0; mt < 4; ++mt) {
        const int co = co0 + warp_m + mt * 16 + rr;
#pragma unroll
        for (int nt = 0; nt < 4; ++nt) {
            int n = n0 + warp_n + nt * 8 + q * 2;
            if (n < XROWS) {
                int b = n / 1156;
                int rem = n - b * 1156;
                float2 v0 = make_float2(acc[mt][nt][0], acc[mt][nt][1]);
                float2 v1 = make_float2(acc[mt][nt][2], acc[mt][nt][3]);
                *(float2*)(g_y + (((size_t)(b * 512 + co) * 4 + p) * 1156 + rem)) = v0;
                *(float2*)(g_y + (((size_t)(b * 512 + co + 8) * 4 + p) * 1156 + rem)) = v1;
            }
        }
    }
}

__global__ __launch_bounds__(256, 2) void k_gemm() {
    extern __shared__ char smem[];
    const uint32_t su = smem_to_u32(smem);
    const int tid = threadIdx.x;
    const int lane = tid & 31, wid = tid >> 5;
    const int warp_m = (wid >> 2) * 64;
    const int warp_n = (wid & 3) * 32;
    const int n0  = blockIdx.x * 128;
    const int co0 = blockIdx.y * 128;

    float acc[4][4][4];
#pragma unroll
    for (int a = 0; a < 4; ++a)
#pragma unroll
        for (int b = 0; b < 4; ++b)
#pragma unroll
            for (int c = 0; c < 4; ++c) acc[a][b][c] = 0.f;

#pragma unroll
    for (int s = 0; s < STAGES - 1; ++s) {
        load_chunk(su, s, s, co0, n0, tid);
        cp_commit();
    }

    for (int g = 0; g < 144; ++g) {
        cp_wait2();                       // oldest (chunk g) resident
        __syncthreads();                  // single barrier per chunk
        if (g + STAGES - 1 < 144)
            load_chunk(su, (g + STAGES - 1) % STAGES, g + STAGES - 1, co0, n0, tid);
        cp_commit();
        do_compute(su + (g % STAGES) * STAGE_BYTES, acc, lane, warp_m, warp_n);
        if (g == 63 || g == 95 || g == 127 || g == 143) {
            const int p = (g == 63) ? 0 : (g == 95) ? 1 : (g == 127) ? 2 : 3;
            epilogue(acc, p, co0, n0, lane, warp_m, warp_n);
#pragma unroll
            for (int a = 0; a < 4; ++a)
#pragma unroll
                for (int b = 0; b < 4; ++b)
#pragma unroll
                    for (int c = 0; c < 4; ++c) acc[a][b][c] = 0.f;
        }
    }
}

// ---------------------------------------------------------------------------
__global__ __launch_bounds__(256) void k_blur(float* __restrict__ z,
                                              const float* __restrict__ bias) {
    __shared__ float ys[67][68];
    const int co = blockIdx.x, b = blockIdx.y;
    const int tid = threadIdx.x;

    for (int idx = tid; idx < 67 * 68; idx += 256) ((float*)ys)[idx] = 0.f;
    __syncthreads();

    const float* yb = g_y + ((size_t)(b * 512 + co)) * 4 * 1156;
    for (int idx = tid; idx < 4 * 33 * 33; idx += 256) {
        int p = idx / 1089, rem = idx - p * 1089;
        int i = rem / 33, j = rem - i * 33;
        float v = yb[(size_t)p * 1156 + (i + 1) * 34 + (j + 1)];
        ys[2 * i + (p >> 1) + 1][2 * j + (p & 1) + 1] = v;
    }
    __syncthreads();

    const float dd = g_d[b * COUT_ + co];
    const float bv = bias[co];
    const int u = tid >> 2;
    const int v0 = (tid & 3) * 16;

    float col[19];
#pragma unroll
    for (int m = 0; m < 19; ++m) {
        col[m] = ys[u][v0 + m] + 3.f * ys[u + 1][v0 + m]
               + 3.f * ys[u + 2][v0 + m] + ys[u + 3][v0 + m];
    }
    float* zp = z + (((size_t)b * COUT_ + co) * 64 + u) * 64 + v0;
#pragma unroll
    for (int m = 0; m < 16; ++m) {
        float h = col[m] + 3.f * col[m + 1] + 3.f * col[m + 2] + col[m + 3];
        zp[m] = dd * (h * (1.f / 16.f)) + bv;
    }
}

// ---------------------------------------------------------------------------
extern "C" void kernel_launch(void* const* d_in, const int* in_sizes, int n_in,
                              void* d_out, int out_size) {
    const float* x    = (const float*)d_in[0];
    const float* w    = (const float*)d_in[1];
    const float* wt   = (const float*)d_in[2];
    const float* bias = (const float*)d_in[3];
    const float* aw   = (const float*)d_in[4];
    const float* ab   = (const float*)d_in[5];
    float* z = (float*)d_out;

    cudaFuncSetAttribute(k_gemm, cudaFuncAttributeMaxDynamicSharedMemorySize,
                         STAGES * STAGE_BYTES);

    k_style<<<B_, CIN_>>>(w, aw, ab);
    k_prepx<<<dim3(34, B_), 256>>>(x);
    k_guard<<<256, 256>>>();
    k_prepw<<<COUT_, 256>>>(wt);
    k_wsq<<<COUT_, CIN_>>>(wt);
    k_demod<<<B_, COUT_>>>();
    k_gemm<<<dim3(NTILES, 4), 256, STAGES * STAGE_BYTES>>>();
    k_blur<<<dim3(COUT_, B_), 256>>>(z, bias);
}

// round 7
// speedup vs baseline: 7.7543x; 1.2812x over previous
#include <cuda_runtime.h>
#include <cuda_fp16.h>
#include <cstdint>

#define B_    16
#define CIN_  512
#define COUT_ 512
#define LAT_  512

#define XROWS  18496            // 16 * 34 * 34
#define XGUARD 64               // front zero rows
#define XTAIL  320              // tail zero rows (covers 256-row B tiles past end)
#define NT2    73               // ceil(18496/256)

// ---------------- device globals (allocation-free scratch) ------------------
__device__ float g_s[B_ * CIN_];
__device__ float g_wsq[COUT_ * CIN_];
__device__ float g_d[B_ * COUT_];
__device__ float g_y[(size_t)B_ * COUT_ * 4 * 1156];     // [b][co][p][34][34]

__device__ __align__(256) __half g_Ah[9ull * 512 * 512];   // [tap][co][ci]
__device__ __align__(256) __half g_Xh[(size_t)(XGUARD + XROWS + XTAIL) * 512];

// tap order grouped by parity: p0={0,2,6,8} p1={1,7} p2={3,5} p3={4}
__constant__ int c_tap[9]   = {0, 2, 6, 8, 1, 7, 3, 5, 4};
// shift[t] = (kh>>1)*34 + (kw>>1), indexed by tap id
__constant__ int c_shift[9] = {0, 0, 1, 0, 0, 1, 34, 34, 35};

// ---------------- helpers ---------------------------------------------------
__device__ __forceinline__ uint32_t smem_to_u32(const void* p) {
    uint32_t a;
    asm("{ .reg .u64 t; cvta.to.shared.u64 t, %1; cvt.u32.u64 %0, t; }"
        : "=r"(a) : "l"(p));
    return a;
}
__device__ __forceinline__ void cp16(uint32_t dst, const void* src) {
    asm volatile("cp.async.cg.shared.global [%0], [%1], 16;\n"
                 :: "r"(dst), "l"(src));
}
__device__ __forceinline__ void cp_commit() {
    asm volatile("cp.async.commit_group;\n" ::: "memory");
}
__device__ __forceinline__ void cp_wait2() {
    asm volatile("cp.async.wait_group 2;\n" ::: "memory");
}
__device__ __forceinline__ void ldsm_x4(uint32_t* r, uint32_t addr) {
    asm volatile("ldmatrix.sync.aligned.m8n8.x4.shared.b16 {%0,%1,%2,%3}, [%4];"
                 : "=r"(r[0]), "=r"(r[1]), "=r"(r[2]), "=r"(r[3]) : "r"(addr));
}
__device__ __forceinline__ void mma_fp16(float* d, const uint32_t* a,
                                         const uint32_t* b) {
    asm volatile(
        "mma.sync.aligned.m16n8k16.row.col.f32.f16.f16.f32 "
        "{%0,%1,%2,%3}, {%4,%5,%6,%7}, {%8,%9}, {%0,%1,%2,%3};"
        : "+f"(d[0]), "+f"(d[1]), "+f"(d[2]), "+f"(d[3])
        : "r"(a[0]), "r"(a[1]), "r"(a[2]), "r"(a[3]), "r"(b[0]), "r"(b[1]));
}
// smem tile rows of 32 fp16 (64B), xor-swizzled 16B chunks
__device__ __forceinline__ int swz(int row, int c8) {
    return row * 64 + ((c8 ^ ((row >> 1) & 3)) << 4);
}

// ---------------------------------------------------------------------------
__global__ void k_style(const float* __restrict__ w, const float* __restrict__ aw,
                        const float* __restrict__ ab) {
    int b = blockIdx.x, ci = threadIdx.x;
    const float* wr = w + b * LAT_;
    const float* ar = aw + (size_t)ci * LAT_;
    float acc = 0.f;
#pragma unroll 8
    for (int l = 0; l < LAT_; ++l) acc += wr[l] * ar[l];
    g_s[b * CIN_ + ci] = acc + ab[ci] + 1.0f;
}

__global__ void k_wsq(const float* __restrict__ weight) {
    int co = blockIdx.x, ci = threadIdx.x;
    const float* p = weight + ((size_t)co * CIN_ + ci) * 9;
    float a = 0.f;
#pragma unroll
    for (int k = 0; k < 9; ++k) a += p[k] * p[k];
    g_wsq[co * CIN_ + ci] = a;
}

__global__ void k_demod() {
    int b = blockIdx.x, co = threadIdx.x;
    __shared__ float s2[CIN_];
    for (int i = threadIdx.x; i < CIN_; i += blockDim.x) {
        float v = g_s[b * CIN_ + i];
        s2[i] = v * v;
    }
    __syncthreads();
    const float* wq = g_wsq + (size_t)co * CIN_;
    float a = 0.f;
#pragma unroll 8
    for (int ci = 0; ci < CIN_; ++ci) a += s2[ci] * wq[ci];
    g_d[b * COUT_ + co] = rsqrtf(a + 1e-8f);
}

// A prep: g_Ah[tap][co][ci] = fp16(weight[co][ci][tap])
__global__ __launch_bounds__(256) void k_prepw(const float* __restrict__ weight) {
    int co = blockIdx.x;
    for (int idx = threadIdx.x; idx < 9 * 512; idx += 256) {
        int t = idx / 512, ci = idx & 511;
        float v = weight[((size_t)co * 512 + ci) * 9 + t];
        g_Ah[((size_t)t * 512 + co) * 512 + ci] = __float2half_rn(v);
    }
}

// Xp prep: row n = b*1156 + r*34 + c ; Xp = x*s interior, 0 on r,c in {0,33}
__global__ __launch_bounds__(256) void k_prepx(const float* __restrict__ x) {
    __shared__ float xt[256][33];
    const int r = blockIdx.x;          // 0..33
    const int b = blockIdx.y;
    const int tid = threadIdx.x;
    const bool irow = (r >= 1 && r <= 32);
    for (int half = 0; half < 2; ++half) {
        const int cb = half * 256;
        __syncthreads();
        if (irow) {
            for (int idx = tid; idx < 256 * 32; idx += 256) {
                int ci = idx >> 5, cc = idx & 31;
                xt[ci][cc] = x[((size_t)(b * 512 + cb + ci) * 32 + (r - 1)) * 32 + cc]
                             * g_s[b * 512 + cb + ci];
            }
        }
        __syncthreads();
        for (int idx = tid; idx < 34 * 256; idx += 256) {
            int c = idx >> 8, ci = idx & 255;
            float v = (irow && c >= 1 && c <= 32) ? xt[ci][c - 1] : 0.f;
            size_t o = ((size_t)(b * 1156 + r * 34 + c) + XGUARD) * 512 + cb + ci;
            g_Xh[o] = __float2half_rn(v);
        }
    }
}

__global__ void k_guard() {
    int idx = blockIdx.x * 256 + threadIdx.x;       // (64+320)*512 = 196608 total
    __half z = __float2half_rn(0.f);
    if (idx < XGUARD * 512) {
        g_Xh[idx] = z;
    } else {
        g_Xh[(size_t)(XGUARD + XROWS) * 512 + (idx - XGUARD * 512)] = z;
    }
}

// ---------------------------------------------------------------------------
// Block tile: 128 co x 256 n x K-chunk 32. Warp tile 64x64 (8 warps, 2x4).
#define STAGES      4
#define TILE_A      0           // 128 x 32 fp16 = 8KB
#define TILE_B      8192        // 256 x 32 fp16 = 16KB
#define STAGE_BYTES 24576

__device__ __forceinline__ void load_chunk(uint32_t su, int stage, int g,
                                           int co0, int n0, int tid) {
    const int tap = c_tap[g >> 4];
    const int kc  = (g & 15) << 5;
    const uint32_t sb = su + stage * STAGE_BYTES;
    // A: 512 cp16
#pragma unroll
    for (int t = 0; t < 2; ++t) {
        int idx = t * 256 + tid;
        int row = idx >> 2, c8 = idx & 3;
        size_t aoff = ((size_t)(tap * 512 + co0 + row)) * 512 + kc + c8 * 8;
        cp16(sb + TILE_A + swz(row, c8), g_Ah + aoff);
    }
    // B: 1024 cp16 (shifted view into padded X)
    const long base = (long)n0 - c_shift[tap] + XGUARD;
#pragma unroll
    for (int t = 0; t < 4; ++t) {
        int idx = t * 256 + tid;
        int row = idx >> 2, c8 = idx & 3;
        size_t boff = (size_t)(base + row) * 512 + kc + c8 * 8;
        cp16(sb + TILE_B + swz(row, c8), g_Xh + boff);
    }
}

__device__ __forceinline__ void do_compute(uint32_t sb, float acc[4][8][4],
                                           int lane, int warp_m, int warp_n) {
#pragma unroll
    for (int ks = 0; ks < 2; ++ks) {
        uint32_t bh[16];
#pragma unroll
        for (int pr = 0; pr < 4; ++pr) {
            int brow = warp_n + pr * 16 + (lane & 7) + ((lane >> 4) & 1) * 8;
            int bc8  = ks * 2 + ((lane >> 3) & 1);
            ldsm_x4(&bh[pr * 4], sb + TILE_B + swz(brow, bc8));
        }
#pragma unroll
        for (int mt = 0; mt < 4; ++mt) {
            int arow = warp_m + mt * 16 + (lane & 15);
            int ac8  = ks * 2 + ((lane >> 4) & 1);
            uint32_t ah[4];
            ldsm_x4(ah, sb + TILE_A + swz(arow, ac8));
#pragma unroll
            for (int nt = 0; nt < 8; ++nt) {
                mma_fp16(acc[mt][nt], ah, &bh[(nt >> 1) * 4 + (nt & 1) * 2]);
            }
        }
    }
}

__device__ __forceinline__ void epilogue(float acc[4][8][4], int p, int co0,
                                         int n0, int lane, int warp_m, int warp_n) {
    const int rr = lane >> 2, q = lane & 3;
#pragma unroll
    for (int mt = 0; mt < 4; ++mt) {
        const int co = co0 + warp_m + mt * 16 + rr;
#pragma unroll
        for (int nt = 0; nt < 8; ++nt) {
            int n = n0 + warp_n + nt * 8 + q * 2;
            if (n < XROWS) {
                int b = n / 1156;
                int rem = n - b * 1156;
                float2 v0 = make_float2(acc[mt][nt][0], acc[mt][nt][1]);
                float2 v1 = make_float2(acc[mt][nt][2], acc[mt][nt][3]);
                *(float2*)(g_y + (((size_t)(b * 512 + co) * 4 + p) * 1156 + rem)) = v0;
                *(float2*)(g_y + (((size_t)(b * 512 + co + 8) * 4 + p) * 1156 + rem)) = v1;
            }
        }
    }
}

__global__ __launch_bounds__(256, 1) void k_gemm() {
    extern __shared__ char smem[];
    const uint32_t su = smem_to_u32(smem);
    const int tid = threadIdx.x;
    const int lane = tid & 31, wid = tid >> 5;
    const int warp_m = (wid >> 2) * 64;
    const int warp_n = (wid & 3) * 64;
    const int n0  = blockIdx.x * 256;
    const int co0 = blockIdx.y * 128;

    float acc[4][8][4];
#pragma unroll
    for (int a = 0; a < 4; ++a)
#pragma unroll
        for (int b = 0; b < 8; ++b)
#pragma unroll
            for (int c = 0; c < 4; ++c) acc[a][b][c] = 0.f;

#pragma unroll
    for (int s = 0; s < STAGES - 1; ++s) {
        load_chunk(su, s, s, co0, n0, tid);
        cp_commit();
    }

    for (int g = 0; g < 144; ++g) {
        cp_wait2();                       // oldest (chunk g) resident
        __syncthreads();                  // single barrier per chunk
        if (g + STAGES - 1 < 144)
            load_chunk(su, (g + STAGES - 1) % STAGES, g + STAGES - 1, co0, n0, tid);
        cp_commit();
        do_compute(su + (g % STAGES) * STAGE_BYTES, acc, lane, warp_m, warp_n);
        if (g == 63 || g == 95 || g == 127 || g == 143) {
            const int p = (g == 63) ? 0 : (g == 95) ? 1 : (g == 127) ? 2 : 3;
            epilogue(acc, p, co0, n0, lane, warp_m, warp_n);
#pragma unroll
            for (int a = 0; a < 4; ++a)
#pragma unroll
                for (int b = 0; b < 8; ++b)
#pragma unroll
                    for (int c = 0; c < 4; ++c) acc[a][b][c] = 0.f;
        }
    }
}

// ---------------------------------------------------------------------------
__global__ __launch_bounds__(256) void k_blur(float* __restrict__ z,
                                              const float* __restrict__ bias) {
    __shared__ float ys[67][68];
    const int co = blockIdx.x, b = blockIdx.y;
    const int tid = threadIdx.x;

    for (int idx = tid; idx < 67 * 68; idx += 256) ((float*)ys)[idx] = 0.f;
    __syncthreads();

    const float* yb = g_y + ((size_t)(b * 512 + co)) * 4 * 1156;
    for (int idx = tid; idx < 4 * 33 * 33; idx += 256) {
        int p = idx / 1089, rem = idx - p * 1089;
        int i = rem / 33, j = rem - i * 33;
        float v = yb[(size_t)p * 1156 + (i + 1) * 34 + (j + 1)];
        ys[2 * i + (p >> 1) + 1][2 * j + (p & 1) + 1] = v;
    }
    __syncthreads();

    const float dd = g_d[b * COUT_ + co];
    const float bv = bias[co];
    const int u = tid >> 2;
    const int v0 = (tid & 3) * 16;

    float col[19];
#pragma unroll
    for (int m = 0; m < 19; ++m) {
        col[m] = ys[u][v0 + m] + 3.f * ys[u + 1][v0 + m]
               + 3.f * ys[u + 2][v0 + m] + ys[u + 3][v0 + m];
    }
    float* zp = z + (((size_t)b * COUT_ + co) * 64 + u) * 64 + v0;
#pragma unroll
    for (int m = 0; m < 16; ++m) {
        float h = col[m] + 3.f * col[m + 1] + 3.f * col[m + 2] + col[m + 3];
        zp[m] = dd * (h * (1.f / 16.f)) + bv;
    }
}

// ---------------------------------------------------------------------------
extern "C" void kernel_launch(void* const* d_in, const int* in_sizes, int n_in,
                              void* d_out, int out_size) {
    const float* x    = (const float*)d_in[0];
    const float* w    = (const float*)d_in[1];
    const float* wt   = (const float*)d_in[2];
    const float* bias = (const float*)d_in[3];
    const float* aw   = (const float*)d_in[4];
    const float* ab   = (const float*)d_in[5];
    float* z = (float*)d_out;

    cudaFuncSetAttribute(k_gemm, cudaFuncAttributeMaxDynamicSharedMemorySize,
                         STAGES * STAGE_BYTES);

    k_style<<<B_, CIN_>>>(w, aw, ab);
    k_prepx<<<dim3(34, B_), 256>>>(x);
    k_guard<<<768, 256>>>();
    k_prepw<<<COUT_, 256>>>(wt);
    k_wsq<<<COUT_, CIN_>>>(wt);
    k_demod<<<B_, COUT_>>>();
    k_gemm<<<dim3(NT2, 4), 256, STAGES * STAGE_BYTES>>>();
    k_blur<<<dim3(COUT_, B_), 256>>>(z, bias);
}

// round 8
// speedup vs baseline: 8.5824x; 1.1068x over previous
#include <cuda_runtime.h>
#include <cuda_fp16.h>
#include <cstdint>

#define B_    16
#define CIN_  512
#define COUT_ 512
#define LAT_  512

#define XROWS  18496            // 16 * 34 * 34
#define XGUARD 64               // front zero rows
#define XTAIL  320              // tail zero rows (covers 256-row B tiles past end)
#define NT2    73               // ceil(18496/256)

// ---------------- device globals (allocation-free scratch) ------------------
__device__ float g_s[B_ * CIN_];
__device__ float g_wsq[COUT_ * CIN_];
__device__ float g_d[B_ * COUT_];
__device__ __half g_y[(size_t)B_ * COUT_ * 4 * 1156];    // [b][co][p][34][34] fp16

__device__ __align__(256) __half g_Ah[9ull * 512 * 512];   // [tap][co][ci]
__device__ __align__(256) __half g_Xh[(size_t)(XGUARD + XROWS + XTAIL) * 512];

// tap order grouped by parity: p0={0,2,6,8} p1={1,7} p2={3,5} p3={4}
__constant__ int c_tap[9]   = {0, 2, 6, 8, 1, 7, 3, 5, 4};
// shift[t] = (kh>>1)*34 + (kw>>1), indexed by tap id
__constant__ int c_shift[9] = {0, 0, 1, 0, 0, 1, 34, 34, 35};

// ---------------- helpers ---------------------------------------------------
__device__ __forceinline__ uint32_t smem_to_u32(const void* p) {
    uint32_t a;
    asm("{ .reg .u64 t; cvta.to.shared.u64 t, %1; cvt.u32.u64 %0, t; }"
        : "=r"(a) : "l"(p));
    return a;
}
__device__ __forceinline__ void cp16(uint32_t dst, const void* src) {
    asm volatile("cp.async.cg.shared.global [%0], [%1], 16;\n"
                 :: "r"(dst), "l"(src));
}
__device__ __forceinline__ void cp_commit() {
    asm volatile("cp.async.commit_group;\n" ::: "memory");
}
__device__ __forceinline__ void cp_wait1() {
    asm volatile("cp.async.wait_group 1;\n" ::: "memory");
}
__device__ __forceinline__ void ldsm_x4(uint32_t* r, uint32_t addr) {
    asm volatile("ldmatrix.sync.aligned.m8n8.x4.shared.b16 {%0,%1,%2,%3}, [%4];"
                 : "=r"(r[0]), "=r"(r[1]), "=r"(r[2]), "=r"(r[3]) : "r"(addr));
}
__device__ __forceinline__ void mma_fp16(float* d, const uint32_t* a,
                                         const uint32_t* b) {
    asm volatile(
        "mma.sync.aligned.m16n8k16.row.col.f32.f16.f16.f32 "
        "{%0,%1,%2,%3}, {%4,%5,%6,%7}, {%8,%9}, {%0,%1,%2,%3};"
        : "+f"(d[0]), "+f"(d[1]), "+f"(d[2]), "+f"(d[3])
        : "r"(a[0]), "r"(a[1]), "r"(a[2]), "r"(a[3]), "r"(b[0]), "r"(b[1]));
}
// smem tile rows of 64 fp16 (128B), xor-swizzled 16B chunks, 8-row period
__device__ __forceinline__ int swz(int row, int c8) {
    return row * 128 + ((c8 ^ (row & 7)) << 4);
}

// ---------------------------------------------------------------------------
__global__ void k_style(const float* __restrict__ w, const float* __restrict__ aw,
                        const float* __restrict__ ab) {
    int b = blockIdx.x, ci = threadIdx.x;
    const float* wr = w + b * LAT_;
    const float* ar = aw + (size_t)ci * LAT_;
    float acc = 0.f;
#pragma unroll 8
    for (int l = 0; l < LAT_; ++l) acc += wr[l] * ar[l];
    g_s[b * CIN_ + ci] = acc + ab[ci] + 1.0f;
}

__global__ void k_demod() {
    int b = blockIdx.x, co = threadIdx.x;
    __shared__ float s2[CIN_];
    for (int i = threadIdx.x; i < CIN_; i += blockDim.x) {
        float v = g_s[b * CIN_ + i];
        s2[i] = v * v;
    }
    __syncthreads();
    const float* wq = g_wsq + (size_t)co * CIN_;
    float a = 0.f;
#pragma unroll 8
    for (int ci = 0; ci < CIN_; ++ci) a += s2[ci] * wq[ci];
    g_d[b * COUT_ + co] = rsqrtf(a + 1e-8f);
}

// A prep + wsq (merged): g_Ah[tap][co][ci] = fp16(weight[co][ci][tap]),
// g_wsq[co][ci] = sum_t weight^2
__global__ __launch_bounds__(256) void k_prepw(const float* __restrict__ weight) {
    const int co = blockIdx.x;
#pragma unroll
    for (int r = 0; r < 2; ++r) {
        const int ci = threadIdx.x * 2 + r;
        const float* p = weight + ((size_t)co * 512 + ci) * 9;
        float sq = 0.f;
#pragma unroll
        for (int t = 0; t < 9; ++t) {
            float v = p[t];
            g_Ah[((size_t)t * 512 + co) * 512 + ci] = __float2half_rn(v);
            sq += v * v;
        }
        g_wsq[(size_t)co * 512 + ci] = sq;
    }
}

// Xp prep: row n = b*1156 + r*34 + c ; Xp = x*s interior, 0 on r,c in {0,33}
__global__ __launch_bounds__(256) void k_prepx(const float* __restrict__ x) {
    __shared__ float xt[256][33];
    const int r = blockIdx.x;          // 0..33
    const int b = blockIdx.y;
    const int tid = threadIdx.x;
    const bool irow = (r >= 1 && r <= 32);
    for (int half = 0; half < 2; ++half) {
        const int cb = half * 256;
        __syncthreads();
        if (irow) {
            for (int idx = tid; idx < 256 * 32; idx += 256) {
                int ci = idx >> 5, cc = idx & 31;
                xt[ci][cc] = x[((size_t)(b * 512 + cb + ci) * 32 + (r - 1)) * 32 + cc]
                             * g_s[b * 512 + cb + ci];
            }
        }
        __syncthreads();
        for (int idx = tid; idx < 34 * 256; idx += 256) {
            int c = idx >> 8, ci = idx & 255;
            float v = (irow && c >= 1 && c <= 32) ? xt[ci][c - 1] : 0.f;
            size_t o = ((size_t)(b * 1156 + r * 34 + c) + XGUARD) * 512 + cb + ci;
            g_Xh[o] = __float2half_rn(v);
        }
    }
}

__global__ void k_guard() {
    int idx = blockIdx.x * 256 + threadIdx.x;       // (64+320)*512 = 196608 total
    __half z = __float2half_rn(0.f);
    if (idx < XGUARD * 512) {
        g_Xh[idx] = z;
    } else {
        g_Xh[(size_t)(XGUARD + XROWS) * 512 + (idx - XGUARD * 512)] = z;
    }
}

// ---------------------------------------------------------------------------
// Block tile: 128 co x 256 n x K-chunk 64. Warp tile 64x64 (8 warps, 2x4).
#define STAGES      3
#define TILE_A      0           // 128 x 64 fp16 = 16KB
#define TILE_B      16384       // 256 x 64 fp16 = 32KB
#define STAGE_BYTES 49152
#define NCHUNK      72          // 9 taps x 8 chunks of 64 ci

__device__ __forceinline__ void load_chunk(uint32_t su, int stage, int g,
                                           int co0, int n0, int tid) {
    const int tap = c_tap[g >> 3];
    const int kc  = (g & 7) << 6;
    const uint32_t sb = su + stage * STAGE_BYTES;
    // A: 128 rows x 8 c8 = 1024 cp16
#pragma unroll
    for (int t = 0; t < 4; ++t) {
        int idx = t * 256 + tid;
        int row = idx >> 3, c8 = idx & 7;
        size_t aoff = ((size_t)(tap * 512 + co0 + row)) * 512 + kc + c8 * 8;
        cp16(sb + TILE_A + swz(row, c8), g_Ah + aoff);
    }
    // B: 256 rows x 8 c8 = 2048 cp16 (shifted view into padded X)
    const long base = (long)n0 - c_shift[tap] + XGUARD;
#pragma unroll
    for (int t = 0; t < 8; ++t) {
        int idx = t * 256 + tid;
        int row = idx >> 3, c8 = idx & 7;
        size_t boff = (size_t)(base + row) * 512 + kc + c8 * 8;
        cp16(sb + TILE_B + swz(row, c8), g_Xh + boff);
    }
}

__device__ __forceinline__ void do_compute(uint32_t sb, float acc[4][8][4],
                                           int lane, int warp_m, int warp_n) {
#pragma unroll
    for (int ks = 0; ks < 4; ++ks) {
        uint32_t bh[16];
#pragma unroll
        for (int pr = 0; pr < 4; ++pr) {
            int brow = warp_n + pr * 16 + (lane & 7) + ((lane >> 4) & 1) * 8;
            int bc8  = ks * 2 + ((lane >> 3) & 1);
            ldsm_x4(&bh[pr * 4], sb + TILE_B + swz(brow, bc8));
        }
#pragma unroll
        for (int mt = 0; mt < 4; ++mt) {
            int arow = warp_m + mt * 16 + (lane & 15);
            int ac8  = ks * 2 + ((lane >> 4) & 1);
            uint32_t ah[4];
            ldsm_x4(ah, sb + TILE_A + swz(arow, ac8));
#pragma unroll
            for (int nt = 0; nt < 8; ++nt) {
                mma_fp16(acc[mt][nt], ah, &bh[(nt >> 1) * 4 + (nt & 1) * 2]);
            }
        }
    }
}

__device__ __forceinline__ void epilogue(float acc[4][8][4], int p, int co0,
                                         int n0, int lane, int warp_m, int warp_n) {
    const int rr = lane >> 2, q = lane & 3;
#pragma unroll
    for (int mt = 0; mt < 4; ++mt) {
        const int co = co0 + warp_m + mt * 16 + rr;
#pragma unroll
        for (int nt = 0; nt < 8; ++nt) {
            int n = n0 + warp_n + nt * 8 + q * 2;
            if (n < XROWS) {
                int b = n / 1156;
                int rem = n - b * 1156;   // even: half2 stays in-row and aligned
                __half2 v0 = __floats2half2_rn(acc[mt][nt][0], acc[mt][nt][1]);
                __half2 v1 = __floats2half2_rn(acc[mt][nt][2], acc[mt][nt][3]);
                *(__half2*)(g_y + (((size_t)(b * 512 + co) * 4 + p) * 1156 + rem)) = v0;
                *(__half2*)(g_y + (((size_t)(b * 512 + co + 8) * 4 + p) * 1156 + rem)) = v1;
            }
        }
    }
}

__global__ __launch_bounds__(256, 1) void k_gemm() {
    extern __shared__ char smem[];
    const uint32_t su = smem_to_u32(smem);
    const int tid = threadIdx.x;
    const int lane = tid & 31, wid = tid >> 5;
    const int warp_m = (wid >> 2) * 64;
    const int warp_n = (wid & 3) * 64;
    const int n0  = blockIdx.x * 256;
    const int co0 = blockIdx.y * 128;

    float acc[4][8][4];
#pragma unroll
    for (int a = 0; a < 4; ++a)
#pragma unroll
        for (int b = 0; b < 8; ++b)
#pragma unroll
            for (int c = 0; c < 4; ++c) acc[a][b][c] = 0.f;

#pragma unroll
    for (int s = 0; s < STAGES - 1; ++s) {
        load_chunk(su, s, s, co0, n0, tid);
        cp_commit();
    }

    for (int g = 0; g < NCHUNK; ++g) {
        cp_wait1();                       // oldest (chunk g) resident
        __syncthreads();                  // single barrier per chunk
        if (g + STAGES - 1 < NCHUNK)
            load_chunk(su, (g + STAGES - 1) % STAGES, g + STAGES - 1, co0, n0, tid);
        cp_commit();
        do_compute(su + (g % STAGES) * STAGE_BYTES, acc, lane, warp_m, warp_n);
        if (g == 31 || g == 47 || g == 63 || g == 71) {
            const int p = (g == 31) ? 0 : (g == 47) ? 1 : (g == 63) ? 2 : 3;
            epilogue(acc, p, co0, n0, lane, warp_m, warp_n);
#pragma unroll
            for (int a = 0; a < 4; ++a)
#pragma unroll
                for (int b = 0; b < 8; ++b)
#pragma unroll
                    for (int c = 0; c < 4; ++c) acc[a][b][c] = 0.f;
        }
    }
}

// ---------------------------------------------------------------------------
__global__ __launch_bounds__(256) void k_blur(float* __restrict__ z,
                                              const float* __restrict__ bias) {
    __shared__ float ys[67][68];
    const int co = blockIdx.x, b = blockIdx.y;
    const int tid = threadIdx.x;

    for (int idx = tid; idx < 67 * 68; idx += 256) ((float*)ys)[idx] = 0.f;
    __syncthreads();

    const __half* yb = g_y + ((size_t)(b * 512 + co)) * 4 * 1156;
    for (int idx = tid; idx < 4 * 33 * 33; idx += 256) {
        int p = idx / 1089, rem = idx - p * 1089;
        int i = rem / 33, j = rem - i * 33;
        float v = __half2float(yb[(size_t)p * 1156 + (i + 1) * 34 + (j + 1)]);
        ys[2 * i + (p >> 1) + 1][2 * j + (p & 1) + 1] = v;
    }
    __syncthreads();

    const float dd = g_d[b * COUT_ + co];
    const float bv = bias[co];
    const int u = tid >> 2;
    const int v0 = (tid & 3) * 16;

    float col[19];
#pragma unroll
    for (int m = 0; m < 19; ++m) {
        col[m] = ys[u][v0 + m] + 3.f * ys[u + 1][v0 + m]
               + 3.f * ys[u + 2][v0 + m] + ys[u + 3][v0 + m];
    }
    float* zp = z + (((size_t)b * COUT_ + co) * 64 + u) * 64 + v0;
#pragma unroll
    for (int m = 0; m < 16; ++m) {
        float h = col[m] + 3.f * col[m + 1] + 3.f * col[m + 2] + col[m + 3];
        zp[m] = dd * (h * (1.f / 16.f)) + bv;
    }
}

// ---------------------------------------------------------------------------
extern "C" void kernel_launch(void* const* d_in, const int* in_sizes, int n_in,
                              void* d_out, int out_size) {
    const float* x    = (const float*)d_in[0];
    const float* w    = (const float*)d_in[1];
    const float* wt   = (const float*)d_in[2];
    const float* bias = (const float*)d_in[3];
    const float* aw   = (const float*)d_in[4];
    const float* ab   = (const float*)d_in[5];
    float* z = (float*)d_out;

    cudaFuncSetAttribute(k_gemm, cudaFuncAttributeMaxDynamicSharedMemorySize,
                         STAGES * STAGE_BYTES);

    // exactly 5 launches before k_gemm so ncu (-s 5 -c 1) profiles k_gemm
    k_style<<<B_, CIN_>>>(w, aw, ab);          // 0
    k_prepx<<<dim3(34, B_), 256>>>(x);         // 1
    k_guard<<<768, 256>>>();                   // 2
    k_prepw<<<COUT_, 256>>>(wt);               // 3
    k_demod<<<B_, COUT_>>>();                  // 4
    k_gemm<<<dim3(NT2, 4), 256, STAGES * STAGE_BYTES>>>();   // 5  <- profiled
    k_blur<<<dim3(COUT_, B_), 256>>>(z, bias); // 6
}